// round 16
// baseline (speedup 1.0000x reference)
#include <cuda_runtime.h>
#include <cuda_bf16.h>
#include <cstdint>

// ---------------- problem constants ----------------
#define NS   12
#define PC   48
#define HID  96
#define HH   512
#define WW   512
#define HW   (HH*WW)
#define CHW  (NS*HW)

#define MT    64          // pixels per tile
#define K1    128         // 4 groups x 32 slots (27 real taps each)
#define N1    96
#define K2    96
#define N2    16

// smem layout (bytes). Rows are 256B (16 granules of 16B); granule XOR (row&7).
#define SOFF_A1   0                         // A1/A2: 64 rows x 256B
#define SZ_A1     (64 * 256)                // 16384
#define SOFF_B1   (SOFF_A1 + SZ_A1)         // B1: 96 rows x 256B
#define SZ_B1     (96 * 256)                // 24576
#define SOFF_B2   (SOFF_B1 + SZ_B1)         // B2: 16 rows x 256B
#define SZ_B2     (16 * 256)                // 4096
#define SOFF_D2   (SOFF_B2 + SZ_B2)         // D2: 64 x 17 f32
#define SZ_D2     (64 * 17 * 4)             // 4352
#define SOFF_BIAS (SOFF_D2 + SZ_D2)
#define SZ_BIAS   (N1 * 4)
#define SMEM_TOTAL (SOFF_BIAS + SZ_BIAS)    // 49792 B -> 3 CTAs/SM

// ---------------- fused weights (device scratch) ----------------
__device__ __nv_bfloat16 g_B1c[N1 * K1];  // (w1 @ pw) bf16, k = 32*(ci/3)+(ci%3)*9+tap
__device__ float g_b1c[N1];               // w1 @ pb + b1

// ---------------- asm helpers ----------------
__device__ __forceinline__ uint32_t smem_u32(const void* p) {
    uint32_t a;
    asm("{ .reg .u64 t; cvta.to.shared.u64 t, %1; cvt.u32.u64 %0, t; }" : "=r"(a) : "l"(p));
    return a;
}
__device__ __forceinline__ uint32_t pack_bf16x2(float lo, float hi) {
    uint32_t r;
    asm("cvt.rn.bf16x2.f32 %0, %1, %2;" : "=r"(r) : "f"(hi), "f"(lo));
    return r;
}
__device__ __forceinline__ void ldsm_x4(uint32_t r[4], uint32_t addr) {
    asm volatile("ldmatrix.sync.aligned.m8n8.x4.shared.b16 {%0,%1,%2,%3}, [%4];"
                 : "=r"(r[0]), "=r"(r[1]), "=r"(r[2]), "=r"(r[3]) : "r"(addr));
}
__device__ __forceinline__ void ldsm_x2(uint32_t r[2], uint32_t addr) {
    asm volatile("ldmatrix.sync.aligned.m8n8.x2.shared.b16 {%0,%1}, [%2];"
                 : "=r"(r[0]), "=r"(r[1]) : "r"(addr));
}
__device__ __forceinline__ void mma_bf16(float d[4], const uint32_t a[4],
                                         uint32_t b0, uint32_t b1) {
    asm volatile(
        "mma.sync.aligned.m16n8k16.row.col.f32.bf16.bf16.f32 "
        "{%0,%1,%2,%3}, {%4,%5,%6,%7}, {%8,%9}, {%0,%1,%2,%3};"
        : "+f"(d[0]), "+f"(d[1]), "+f"(d[2]), "+f"(d[3])
        : "r"(a[0]), "r"(a[1]), "r"(a[2]), "r"(a[3]), "r"(b0), "r"(b1));
}

// ---------------- setup: fuse conv weights into MLP1 (bf16) ----------------
__global__ void ca_setup_kernel(const float* __restrict__ pw, const float* __restrict__ pb,
                                const float* __restrict__ w1, const float* __restrict__ b1)
{
    int f = blockIdx.x;        // 0..95
    int k = threadIdx.x;       // 0..127
    int grp = k >> 5, slot = k & 31;
    float acc = 0.f;
    if (slot < 27) {
        int ci = 3 * grp + slot / 9;
        int tap = slot % 9;
        #pragma unroll
        for (int c = 0; c < PC; c++)
            acc = fmaf(w1[f * PC + c], pw[(c * NS + ci) * 9 + tap], acc);
    }
    g_B1c[f * K1 + k] = __float2bfloat16(acc);
    if (k == 0) {
        float b = b1[f];
        for (int c = 0; c < PC; c++) b = fmaf(w1[f * PC + c], pb[c], b);
        g_b1c[f] = b;
    }
}

// ---------------- main kernel ----------------
__global__ __launch_bounds__(256, 3)
void ca_mma_kernel(const float* __restrict__ x,
                   const float* __restrict__ w2,
                   const int*   __restrict__ mask,
                   float* __restrict__ out)
{
    extern __shared__ __align__(256) char smem[];
    const uint32_t su  = smem_u32(smem);
    const uint32_t sbA = su + SOFF_A1;
    const uint32_t sbB1= su + SOFF_B1;
    const uint32_t sbB2= su + SOFF_B2;
    float* D2s   = (float*)(smem + SOFF_D2);    // [64][17]
    float* biass = (float*)(smem + SOFF_BIAS);  // [96]

    const int tid  = threadIdx.x;
    const int wid  = tid >> 5;
    const int lane = tid & 31;
    const int sw   = lane & 7;
    const int par  = wid & 1;              // n-half: [48*par, 48*par+48)
    const int m0   = (wid >> 1) * 16;
    const int n    = blockIdx.z;
    const int h    = blockIdx.y;

    // -------- stage constant weights (once per CTA) --------
    {   // B1: [f][k] bf16, granule-copy with XOR swizzle
        const uint16_t* src = (const uint16_t*)g_B1c;
        for (int i = tid; i < N1 * 16; i += 256) {
            int f = i >> 4, gj = i & 15;
            uint4 q = *(const uint4*)(src + f * K1 + gj * 8);
            *(uint4*)(smem + SOFF_B1 + f * 256 + 16 * (gj ^ (f & 7))) = q;
        }
    }
    for (int i = tid; i < N2 * K2; i += 256) { // B2: w2[o][f] -> [n=o][k=f]
        int o = i / K2, k = i - o * K2;
        __nv_bfloat16 v = (o < NS) ? __float2bfloat16(w2[o * HID + k])
                                   : __float2bfloat16(0.f);
        *(__nv_bfloat16*)(smem + SOFF_B2 + o * 256 + 16 * ((k >> 3) ^ (o & 7)) + 2 * (k & 7)) = v;
    }
    if (tid < N1) biass[tid] = g_b1c[tid];
    __syncthreads();

    // bias regs for this warp's 6 n-tiles
    const int t = lane & 3, g = lane >> 2;
    float bx[6], by[6];
    #pragma unroll
    for (int nt = 0; nt < 6; nt++) {
        bx[nt] = biass[par * 48 + nt * 8 + 2 * t];
        by[nt] = biass[par * 48 + nt * 8 + 2 * t + 1];
    }

    // ldmatrix per-lane address components
    const uint32_t aA_row = sbA + (uint32_t)(m0 + 8 * ((lane >> 3) & 1) + sw) * 256;
    const int akg = lane >> 4;                   // 0/1 : k-granule offset
    const uint32_t bB_row = sbB1 + (uint32_t)(par * 48 + 8 * (lane >> 4) + sw) * 256;
    const int bkg = (lane >> 3) & 1;
    const uint32_t bB2_row = sbB2 + (uint32_t)(par * 8 + sw) * 256;
    const int b2kg = (lane >> 3) & 1;            // lanes 16-31 mirror 0-15

    const float* xn = x + (size_t)n * CHW;
    const int p  = tid & 63;               // pixel within tile
    const int qh = tid >> 6;               // channel group 0..3 (3 ch each)

    for (int it = 0; it < 8; it++) {
        const int w0  = it << 6;
        const int gwm = (w0 + p + WW - 1) & (WW - 1);
        const int gw0 = w0 + p;
        const int gwp = (w0 + p + 1) & (WW - 1);

        // -------- stage im2col A1: 27 taps -> 4 x STS.128, XOR swizzle ----
        float vals[27];
        #pragma unroll
        for (int cc = 0; cc < 3; cc++) {
            const int ci = 3 * qh + cc;
            #pragma unroll
            for (int dh = 0; dh < 3; dh++) {
                const int gh = (h + dh - 1) & (HH - 1);
                const float* rp = xn + (size_t)ci * HW + (size_t)gh * WW;
                vals[cc * 9 + dh * 3 + 0] = __ldg(rp + gwm);
                vals[cc * 9 + dh * 3 + 1] = __ldg(rp + gw0);
                vals[cc * 9 + dh * 3 + 2] = __ldg(rp + gwp);
            }
        }
        float xcen[3] = { vals[4], vals[13], vals[22] };
        #pragma unroll
        for (int j = 0; j < 4; j++) {
            uint32_t q[4];
            #pragma unroll
            for (int wq = 0; wq < 4; wq++) {
                const int s0 = 8 * j + 2 * wq;
                float lo = (s0     < 27) ? vals[s0]     : 0.f;
                float hi = (s0 + 1 < 27) ? vals[s0 + 1] : 0.f;
                q[wq] = pack_bf16x2(lo, hi);
            }
            const int gran = (4 * qh + j) ^ (p & 7);
            *(uint4*)(smem + SOFF_A1 + p * 256 + gran * 16) =
                make_uint4(q[0], q[1], q[2], q[3]);
        }
        __syncthreads();

        // -------- GEMM1: [64 x 128] x [128 x 48(half)] --------
        float acc[6][4];
        #pragma unroll
        for (int nt = 0; nt < 6; nt++)
            #pragma unroll
            for (int q = 0; q < 4; q++) acc[nt][q] = 0.f;

        #pragma unroll
        for (int ks = 0; ks < 8; ks++) {
            const int kg = 2 * ks;
            uint32_t a[4];
            ldsm_x4(a, aA_row + 16u * ((kg + akg) ^ sw));
            #pragma unroll
            for (int pr = 0; pr < 3; pr++) {
                uint32_t b[4];
                ldsm_x4(b, bB_row + pr * (16u * 256u) + 16u * ((kg + bkg) ^ sw));
                mma_bf16(acc[2 * pr],     a, b[0], b[1]);
                mma_bf16(acc[2 * pr + 1], a, b[2], b[3]);
            }
        }
        __syncthreads();   // all warps done reading A1 before A2 overwrite

        // -------- epilogue 1: bias + relu -> A2 bf16 [p][f] --------
        #pragma unroll
        for (int nt = 0; nt < 6; nt++) {
            const int fg = par * 6 + nt;                 // f-granule
            float h00 = fmaxf(acc[nt][0] + bx[nt], 0.f);
            float h01 = fmaxf(acc[nt][1] + by[nt], 0.f);
            float h10 = fmaxf(acc[nt][2] + bx[nt], 0.f);
            float h11 = fmaxf(acc[nt][3] + by[nt], 0.f);
            *(uint32_t*)(smem + SOFF_A1 + (m0 + g) * 256 + 16 * (fg ^ g) + 4 * t)
                = pack_bf16x2(h00, h01);
            *(uint32_t*)(smem + SOFF_A1 + (m0 + g + 8) * 256 + 16 * (fg ^ g) + 4 * t)
                = pack_bf16x2(h10, h11);
        }
        __syncthreads();

        // -------- GEMM2: [64 x 96] x [96 x 8(half)] --------
        float acc2[4] = {0.f, 0.f, 0.f, 0.f};
        #pragma unroll
        for (int ks = 0; ks < 6; ks++) {
            const int kg = 2 * ks;
            uint32_t a[4];
            ldsm_x4(a, aA_row + 16u * ((kg + akg) ^ sw));
            uint32_t b[2];
            ldsm_x2(b, bB2_row + 16u * ((kg + b2kg) ^ sw));
            mma_bf16(acc2, a, b[0], b[1]);
        }

        // -------- D2 fragments --------
        {
            const int c0 = par * 8 + 2 * t;
            D2s[(m0 + g    ) * 17 + c0    ] = acc2[0];
            D2s[(m0 + g    ) * 17 + c0 + 1] = acc2[1];
            D2s[(m0 + g + 8) * 17 + c0    ] = acc2[2];
            D2s[(m0 + g + 8) * 17 + c0 + 1] = acc2[3];
        }
        __syncthreads();

        // -------- masked residual + coalesced store (3 ch/thread) ----
        {
            const size_t pix = (size_t)n * CHW + (size_t)h * WW + (size_t)(w0 + p);
            #pragma unroll
            for (int cc = 0; cc < 3; cc++) {
                const int c = 3 * qh + cc;
                int m = mask[pix + (size_t)c * HW];
                float u = D2s[p * 17 + c];
                out[pix + (size_t)c * HW] = xcen[cc] + (m ? u : 0.f);
            }
        }
        __syncthreads();   // D2/A2 reads done before next iteration's writes
    }
}

// ---------------- launch ----------------
extern "C" void kernel_launch(void* const* d_in, const int* in_sizes, int n_in,
                              void* d_out, int out_size)
{
    const float* x    = (const float*)d_in[0];
    const float* pw   = (const float*)d_in[1];
    const float* pb   = (const float*)d_in[2];
    const float* w1   = (const float*)d_in[3];
    const float* b1   = (const float*)d_in[4];
    const float* w2   = (const float*)d_in[5];
    const int*   mask = (const int*)  d_in[6];
    float* out = (float*)d_out;

    static bool attr_set = false;
    if (!attr_set) {
        cudaFuncSetAttribute(ca_mma_kernel,
                             cudaFuncAttributeMaxDynamicSharedMemorySize,
                             SMEM_TOTAL);
        attr_set = true;
    }

    ca_setup_kernel<<<N1, 128>>>(pw, pb, w1, b1);

    dim3 grid(1, HH, 8);          // 4096 CTAs, 8 tiles (64px) each
    ca_mma_kernel<<<grid, 256, SMEM_TOTAL>>>(x, w2, mask, out);
}

// round 17
// speedup vs baseline: 1.0118x; 1.0118x over previous
#include <cuda_runtime.h>
#include <cuda_bf16.h>
#include <cstdint>

// ---------------- problem constants ----------------
#define NS   12
#define PC   48
#define HID  96
#define HH   512
#define WW   512
#define HW   (HH*WW)
#define CHW  (NS*HW)

#define MT    64          // pixels per tile
#define K1    128         // 4 groups x 32 slots (27 real taps each)
#define N1    96
#define K2    96
#define N2    16

// smem layout (bytes). Rows are 256B (16 granules of 16B); granule XOR (row&7).
#define SOFF_A1   0                         // A1/A2: 64 rows x 256B
#define SZ_A1     (64 * 256)                // 16384
#define SOFF_B1   (SOFF_A1 + SZ_A1)         // B1: 96 rows x 256B
#define SZ_B1     (96 * 256)                // 24576
#define SOFF_B2   (SOFF_B1 + SZ_B1)         // B2: 16 rows x 256B
#define SZ_B2     (16 * 256)                // 4096
#define SOFF_D2   (SOFF_B2 + SZ_B2)         // D2: 64 x 17 f32
#define SZ_D2     (64 * 17 * 4)             // 4352
#define SOFF_BIAS (SOFF_D2 + SZ_D2)
#define SZ_BIAS   (N1 * 4)
#define SMEM_TOTAL (SOFF_BIAS + SZ_BIAS)    // 49792 B -> 3 CTAs/SM

// ---------------- fused weights (device scratch) ----------------
__device__ __nv_bfloat16 g_B1c[N1 * K1];  // (w1 @ pw) bf16, k = 32*(ci/3)+(ci%3)*9+tap
__device__ float g_b1c[N1];               // w1 @ pb + b1

// ---------------- asm helpers ----------------
__device__ __forceinline__ uint32_t smem_u32(const void* p) {
    uint32_t a;
    asm("{ .reg .u64 t; cvta.to.shared.u64 t, %1; cvt.u32.u64 %0, t; }" : "=r"(a) : "l"(p));
    return a;
}
__device__ __forceinline__ uint32_t pack_bf16x2(float lo, float hi) {
    uint32_t r;
    asm("cvt.rn.bf16x2.f32 %0, %1, %2;" : "=r"(r) : "f"(hi), "f"(lo));
    return r;
}
__device__ __forceinline__ void ldsm_x4(uint32_t r[4], uint32_t addr) {
    asm volatile("ldmatrix.sync.aligned.m8n8.x4.shared.b16 {%0,%1,%2,%3}, [%4];"
                 : "=r"(r[0]), "=r"(r[1]), "=r"(r[2]), "=r"(r[3]) : "r"(addr));
}
__device__ __forceinline__ void ldsm_x2(uint32_t r[2], uint32_t addr) {
    asm volatile("ldmatrix.sync.aligned.m8n8.x2.shared.b16 {%0,%1}, [%2];"
                 : "=r"(r[0]), "=r"(r[1]) : "r"(addr));
}
__device__ __forceinline__ void mma_bf16(float d[4], const uint32_t a[4],
                                         uint32_t b0, uint32_t b1) {
    asm volatile(
        "mma.sync.aligned.m16n8k16.row.col.f32.bf16.bf16.f32 "
        "{%0,%1,%2,%3}, {%4,%5,%6,%7}, {%8,%9}, {%0,%1,%2,%3};"
        : "+f"(d[0]), "+f"(d[1]), "+f"(d[2]), "+f"(d[3])
        : "r"(a[0]), "r"(a[1]), "r"(a[2]), "r"(a[3]), "r"(b0), "r"(b1));
}

// ---------------- setup: fuse conv weights into MLP1 (bf16) ----------------
__global__ void ca_setup_kernel(const float* __restrict__ pw, const float* __restrict__ pb,
                                const float* __restrict__ w1, const float* __restrict__ b1)
{
    int f = blockIdx.x;        // 0..95
    int k = threadIdx.x;       // 0..127
    int grp = k >> 5, slot = k & 31;
    float acc = 0.f;
    if (slot < 27) {
        int ci = 3 * grp + slot / 9;
        int tap = slot % 9;
        #pragma unroll
        for (int c = 0; c < PC; c++)
            acc = fmaf(w1[f * PC + c], pw[(c * NS + ci) * 9 + tap], acc);
    }
    g_B1c[f * K1 + k] = __float2bfloat16(acc);
    if (k == 0) {
        float b = b1[f];
        for (int c = 0; c < PC; c++) b = fmaf(w1[f * PC + c], pb[c], b);
        g_b1c[f] = b;
    }
}

// ---------------- main kernel ----------------
__global__ __launch_bounds__(256, 3)
void ca_mma_kernel(const float* __restrict__ x,
                   const float* __restrict__ w2,
                   const int*   __restrict__ mask,
                   float* __restrict__ out)
{
    extern __shared__ __align__(256) char smem[];
    const uint32_t su  = smem_u32(smem);
    const uint32_t sbA = su + SOFF_A1;
    const uint32_t sbB1= su + SOFF_B1;
    const uint32_t sbB2= su + SOFF_B2;
    float* D2s   = (float*)(smem + SOFF_D2);    // [64][17]
    float* biass = (float*)(smem + SOFF_BIAS);  // [96]

    const int tid  = threadIdx.x;
    const int wid  = tid >> 5;
    const int lane = tid & 31;
    const int sw   = lane & 7;
    const int par  = wid & 1;              // n-half: [48*par, 48*par+48)
    const int m0   = (wid >> 1) * 16;
    const int n    = blockIdx.z;
    const int h    = blockIdx.y;

    // -------- stage constant weights (once per CTA) --------
    {   // B1: [f][k] bf16, granule-copy with XOR swizzle
        const uint16_t* src = (const uint16_t*)g_B1c;
        for (int i = tid; i < N1 * 16; i += 256) {
            int f = i >> 4, gj = i & 15;
            uint4 q = *(const uint4*)(src + f * K1 + gj * 8);
            *(uint4*)(smem + SOFF_B1 + f * 256 + 16 * (gj ^ (f & 7))) = q;
        }
    }
    for (int i = tid; i < N2 * K2; i += 256) { // B2: w2[o][f] -> [n=o][k=f]
        int o = i / K2, k = i - o * K2;
        __nv_bfloat16 v = (o < NS) ? __float2bfloat16(w2[o * HID + k])
                                   : __float2bfloat16(0.f);
        *(__nv_bfloat16*)(smem + SOFF_B2 + o * 256 + 16 * ((k >> 3) ^ (o & 7)) + 2 * (k & 7)) = v;
    }
    if (tid < N1) biass[tid] = g_b1c[tid];
    __syncthreads();

    // bias regs for this warp's 6 n-tiles
    const int t = lane & 3, g = lane >> 2;
    float bx[6], by[6];
    #pragma unroll
    for (int nt = 0; nt < 6; nt++) {
        bx[nt] = biass[par * 48 + nt * 8 + 2 * t];
        by[nt] = biass[par * 48 + nt * 8 + 2 * t + 1];
    }

    // ldmatrix per-lane address components
    const uint32_t aA_row = sbA + (uint32_t)(m0 + 8 * ((lane >> 3) & 1) + sw) * 256;
    const int akg = lane >> 4;                   // 0/1 : k-granule offset
    const uint32_t bB_row = sbB1 + (uint32_t)(par * 48 + 8 * (lane >> 4) + sw) * 256;
    const int bkg = (lane >> 3) & 1;
    const uint32_t bB2_row = sbB2 + (uint32_t)(par * 8 + sw) * 256;
    const int b2kg = (lane >> 3) & 1;            // lanes 16-31 mirror 0-15

    const float* xn = x + (size_t)n * CHW;
    const int p  = tid & 63;               // pixel within tile
    const int qh = tid >> 6;               // channel group 0..3 (3 ch each)

    for (int it = 0; it < 8; it++) {
        const int w0  = it << 6;
        const int gwm = (w0 + p + WW - 1) & (WW - 1);
        const int gw0 = w0 + p;
        const int gwp = (w0 + p + 1) & (WW - 1);

        // -------- stage im2col A1: 27 taps -> 4 x STS.128, XOR swizzle ----
        float vals[27];
        #pragma unroll
        for (int cc = 0; cc < 3; cc++) {
            const int ci = 3 * qh + cc;
            #pragma unroll
            for (int dh = 0; dh < 3; dh++) {
                const int gh = (h + dh - 1) & (HH - 1);
                const float* rp = xn + (size_t)ci * HW + (size_t)gh * WW;
                vals[cc * 9 + dh * 3 + 0] = __ldg(rp + gwm);
                vals[cc * 9 + dh * 3 + 1] = __ldg(rp + gw0);
                vals[cc * 9 + dh * 3 + 2] = __ldg(rp + gwp);
            }
        }
        float xcen[3] = { vals[4], vals[13], vals[22] };
        #pragma unroll
        for (int j = 0; j < 4; j++) {
            uint32_t q[4];
            #pragma unroll
            for (int wq = 0; wq < 4; wq++) {
                const int s0 = 8 * j + 2 * wq;
                float lo = (s0     < 27) ? vals[s0]     : 0.f;
                float hi = (s0 + 1 < 27) ? vals[s0 + 1] : 0.f;
                q[wq] = pack_bf16x2(lo, hi);
            }
            const int gran = (4 * qh + j) ^ (p & 7);
            *(uint4*)(smem + SOFF_A1 + p * 256 + gran * 16) =
                make_uint4(q[0], q[1], q[2], q[3]);
        }
        __syncthreads();

        // -------- GEMM1: [64 x 128] x [128 x 48(half)] --------
        float acc[6][4];
        #pragma unroll
        for (int nt = 0; nt < 6; nt++)
            #pragma unroll
            for (int q = 0; q < 4; q++) acc[nt][q] = 0.f;

        #pragma unroll
        for (int ks = 0; ks < 8; ks++) {
            const int kg = 2 * ks;
            uint32_t a[4];
            ldsm_x4(a, aA_row + 16u * ((kg + akg) ^ sw));
            #pragma unroll
            for (int pr = 0; pr < 3; pr++) {
                uint32_t b[4];
                ldsm_x4(b, bB_row + pr * (16u * 256u) + 16u * ((kg + bkg) ^ sw));
                mma_bf16(acc[2 * pr],     a, b[0], b[1]);
                mma_bf16(acc[2 * pr + 1], a, b[2], b[3]);
            }
        }
        __syncthreads();   // all warps done reading A1 before A2 overwrite

        // -------- epilogue 1: bias + relu -> A2 bf16 [p][f] --------
        #pragma unroll
        for (int nt = 0; nt < 6; nt++) {
            const int fg = par * 6 + nt;                 // f-granule
            float h00 = fmaxf(acc[nt][0] + bx[nt], 0.f);
            float h01 = fmaxf(acc[nt][1] + by[nt], 0.f);
            float h10 = fmaxf(acc[nt][2] + bx[nt], 0.f);
            float h11 = fmaxf(acc[nt][3] + by[nt], 0.f);
            *(uint32_t*)(smem + SOFF_A1 + (m0 + g) * 256 + 16 * (fg ^ g) + 4 * t)
                = pack_bf16x2(h00, h01);
            *(uint32_t*)(smem + SOFF_A1 + (m0 + g + 8) * 256 + 16 * (fg ^ g) + 4 * t)
                = pack_bf16x2(h10, h11);
        }
        __syncthreads();

        // -------- GEMM2: [64 x 96] x [96 x 8(half)] --------
        float acc2[4] = {0.f, 0.f, 0.f, 0.f};
        #pragma unroll
        for (int ks = 0; ks < 6; ks++) {
            const int kg = 2 * ks;
            uint32_t a[4];
            ldsm_x4(a, aA_row + 16u * ((kg + akg) ^ sw));
            uint32_t b[2];
            ldsm_x2(b, bB2_row + 16u * ((kg + b2kg) ^ sw));
            mma_bf16(acc2, a, b[0], b[1]);
        }

        // -------- D2 fragments --------
        {
            const int c0 = par * 8 + 2 * t;
            D2s[(m0 + g    ) * 17 + c0    ] = acc2[0];
            D2s[(m0 + g    ) * 17 + c0 + 1] = acc2[1];
            D2s[(m0 + g + 8) * 17 + c0    ] = acc2[2];
            D2s[(m0 + g + 8) * 17 + c0 + 1] = acc2[3];
        }
        __syncthreads();

        // -------- masked residual + coalesced store (3 ch/thread) ----
        {
            const size_t pix = (size_t)n * CHW + (size_t)h * WW + (size_t)(w0 + p);
            #pragma unroll
            for (int cc = 0; cc < 3; cc++) {
                const int c = 3 * qh + cc;
                int m = mask[pix + (size_t)c * HW];
                float u = D2s[p * 17 + c];
                out[pix + (size_t)c * HW] = xcen[cc] + (m ? u : 0.f);
            }
        }
        __syncthreads();   // D2/A2 reads done before next iteration's writes
    }
}

// ---------------- launch ----------------
extern "C" void kernel_launch(void* const* d_in, const int* in_sizes, int n_in,
                              void* d_out, int out_size)
{
    const float* x    = (const float*)d_in[0];
    const float* pw   = (const float*)d_in[1];
    const float* pb   = (const float*)d_in[2];
    const float* w1   = (const float*)d_in[3];
    const float* b1   = (const float*)d_in[4];
    const float* w2   = (const float*)d_in[5];
    const int*   mask = (const int*)  d_in[6];
    float* out = (float*)d_out;

    static bool attr_set = false;
    if (!attr_set) {
        cudaFuncSetAttribute(ca_mma_kernel,
                             cudaFuncAttributeMaxDynamicSharedMemorySize,
                             SMEM_TOTAL);
        attr_set = true;
    }

    ca_setup_kernel<<<N1, 128>>>(pw, pb, w1, b1);

    dim3 grid(1, HH, 8);          // 4096 CTAs, 8 tiles (64px) each
    ca_mma_kernel<<<grid, 256, SMEM_TOTAL>>>(x, w2, mask, out);
}